// round 13
// baseline (speedup 1.0000x reference)
#include <cuda_runtime.h>
#include <cuda_fp16.h>

typedef unsigned int u32;

#define TPB 256
#define NW  8    // warps per CTA

// SMEM: B-frag bank 32KB | consts 2KB | stash: 8 warps x 2 chunks x 48 float2/lane
#define CONST_OFF 32768
#define STASH_OFF (32768 + 2048)
#define SMEM_BYTES (STASH_OFF + NW * 2 * 96 * 32 * 4)   // 231424

__device__ __forceinline__ float ftanh(float x) {
    float r; asm("tanh.approx.f32 %0, %1;" : "=f"(r) : "f"(x));
    return r;
}

__device__ __forceinline__ u32 pack2h(float a, float b) {
    __half2 h2 = __floats2half2_rn(a, b);
    return *reinterpret_cast<u32*>(&h2);
}

// accumulate form: D = A*B + D
__device__ __forceinline__ void mma16816(float* d, const u32* a, u32 b0, u32 b1) {
    asm volatile(
        "mma.sync.aligned.m16n8k16.row.col.f32.f16.f16.f32 "
        "{%0,%1,%2,%3},{%4,%5,%6,%7},{%8,%9},{%0,%1,%2,%3};"
        : "+f"(d[0]), "+f"(d[1]), "+f"(d[2]), "+f"(d[3])
        : "r"(a[0]), "r"(a[1]), "r"(a[2]), "r"(a[3]), "r"(b0), "r"(b1));
}
// zero-C form: D = A*B + 0
__device__ __forceinline__ void mma16816_z(float* d, const u32* a, u32 b0, u32 b1) {
    asm volatile(
        "mma.sync.aligned.m16n8k16.row.col.f32.f16.f16.f32 "
        "{%0,%1,%2,%3},{%4,%5,%6,%7},{%8,%9},{%10,%11,%12,%13};"
        : "=f"(d[0]), "=f"(d[1]), "=f"(d[2]), "=f"(d[3])
        : "r"(a[0]), "r"(a[1]), "r"(a[2]), "r"(a[3]), "r"(b0), "r"(b1),
          "f"(0.0f), "f"(0.0f), "f"(0.0f), "f"(0.0f));
}

// One GEMM stage for chunk C: value = Ah x Bh, tangent = Th x Bh.
#define RUN_STAGE(S, C) do {                                                  \
    _Pragma("unroll")                                                         \
    for (int kt = 0; kt < 4; kt++) {                                          \
        _Pragma("unroll")                                                     \
        for (int nt = 0; nt < 8; nt++) {                                      \
            uint2 bf = bfr[(((S) * 4 + kt) * 8 + nt) * 32 + lane];            \
            if (kt == 0) {                                                    \
                mma16816_z(zacc[C][nt], Ah[C][kt], bf.x, bf.y);               \
                mma16816_z(dacc[C][nt], Th[C][kt], bf.x, bf.y);               \
            } else {                                                          \
                mma16816(zacc[C][nt], Ah[C][kt], bf.x, bf.y);                 \
                mma16816(dacc[C][nt], Th[C][kt], bf.x, bf.y);                 \
            }                                                                 \
        }                                                                     \
    }                                                                         \
} while (0)

#define PACK_AFRAGS(C) do {                                                   \
    _Pragma("unroll")                                                         \
    for (int kt = 0; kt < 4; kt++) {                                          \
        Ah[C][kt][0] = pack2h(zacc[C][2*kt][0],   zacc[C][2*kt][1]);          \
        Ah[C][kt][1] = pack2h(zacc[C][2*kt][2],   zacc[C][2*kt][3]);          \
        Ah[C][kt][2] = pack2h(zacc[C][2*kt+1][0], zacc[C][2*kt+1][1]);        \
        Ah[C][kt][3] = pack2h(zacc[C][2*kt+1][2], zacc[C][2*kt+1][3]);        \
        Th[C][kt][0] = pack2h(dacc[C][2*kt][0],   dacc[C][2*kt][1]);          \
        Th[C][kt][1] = pack2h(dacc[C][2*kt][2],   dacc[C][2*kt][3]);          \
        Th[C][kt][2] = pack2h(dacc[C][2*kt+1][0], dacc[C][2*kt+1][1]);        \
        Th[C][kt][3] = pack2h(dacc[C][2*kt+1][2], dacc[C][2*kt+1][3]);        \
    }                                                                         \
} while (0)

// F0: build h0/hd0 A-frags for chunk C, stash h0 pairs
#define EW0(C) do {                                                           \
    _Pragma("unroll")                                                         \
    for (int kt = 0; kt < 4; kt++) {                                          \
        _Pragma("unroll")                                                     \
        for (int hh = 0; hh < 2; hh++) {                                      \
            int k = kt * 16 + hh * 8 + qc;                                    \
            int pb = (kt * 2 + hh) * 2;                                       \
            float wa = w00f[k], wb = w00f[k+1];                               \
            float wc = w01f[k], wd = w01f[k+1];                               \
            float ba = b0f[k],  bb = b0f[k+1];                                \
            float z00 = fmaf(xa[C].x, wa, fmaf(xa[C].y, wc, ba));             \
            float z01 = fmaf(xa[C].x, wb, fmaf(xa[C].y, wd, bb));             \
            float z10 = fmaf(xb[C].x, wa, fmaf(xb[C].y, wc, ba));             \
            float z11 = fmaf(xb[C].x, wb, fmaf(xb[C].y, wd, bb));             \
            float h00 = ftanh(z00), h01 = ftanh(z01);                         \
            float h10 = ftanh(z10), h11 = ftanh(z11);                         \
            sp[C][(pb + 0) * 32] = make_float2(h00, h10);                     \
            sp[C][(pb + 1) * 32] = make_float2(h01, h11);                     \
            float d00 = fmaf(-h00, h00, 1.f) * wc;                            \
            float d01 = fmaf(-h01, h01, 1.f) * wd;                            \
            float d10 = fmaf(-h10, h10, 1.f) * wc;                            \
            float d11 = fmaf(-h11, h11, 1.f) * wd;                            \
            Ah[C][kt][hh*2]   = pack2h(h00, h01);                             \
            Ah[C][kt][hh*2+1] = pack2h(h10, h11);                             \
            Th[C][kt][hh*2]   = pack2h(d00, d01);                             \
            Th[C][kt][hh*2+1] = pack2h(d10, d11);                             \
        }                                                                     \
    }                                                                         \
} while (0)

// F1: z1 -> h1,hd1 (stash pairs) -> A-frags
#define EW1(C) do {                                                           \
    _Pragma("unroll")                                                         \
    for (int nt = 0; nt < 8; nt++) {                                          \
        _Pragma("unroll")                                                     \
        for (int j = 0; j < 4; j++) {                                         \
            int col = nt * 8 + qc + (j & 1);                                  \
            float h = ftanh(zacc[C][nt][j] + b1f[col]);                       \
            float u = fmaf(-h, h, 1.f);                                       \
            float hd = u * dacc[C][nt][j];                                    \
            sp[C][(16 + nt * 4 + j) * 32] = make_float2(h, hd);               \
            zacc[C][nt][j] = h; dacc[C][nt][j] = hd;                          \
        }                                                                     \
    }                                                                         \
    PACK_AFRAGS(C);                                                           \
} while (0)

// F2: z2 -> d2, dd2 -> A-frags
#define EW2(C) do {                                                           \
    _Pragma("unroll")                                                         \
    for (int nt = 0; nt < 8; nt++) {                                          \
        _Pragma("unroll")                                                     \
        for (int j = 0; j < 4; j++) {                                         \
            int col = nt * 8 + qc + (j & 1);                                  \
            float h = ftanh(zacc[C][nt][j] + b2f[col]);                       \
            float u = fmaf(-h, h, 1.f);                                       \
            float hd = u * dacc[C][nt][j];                                    \
            float w3v = w3f[col];                                             \
            zacc[C][nt][j] = w3v * u;                                         \
            dacc[C][nt][j] = -2.f * w3v * h * hd;                             \
        }                                                                     \
    }                                                                         \
    PACK_AFRAGS(C);                                                           \
} while (0)

// B1: g1,gd1 -> d1,dd1 (stash load) -> A-frags
#define EW3(C) do {                                                           \
    _Pragma("unroll")                                                         \
    for (int nt = 0; nt < 8; nt++) {                                          \
        _Pragma("unroll")                                                     \
        for (int j = 0; j < 4; j++) {                                         \
            float g = zacc[C][nt][j], gd = dacc[C][nt][j];                    \
            float2 hp = sp[C][(16 + nt * 4 + j) * 32];                        \
            float h = hp.x, hd = hp.y;                                        \
            float u = fmaf(-h, h, 1.f);                                       \
            zacc[C][nt][j] = g * u;                                           \
            dacc[C][nt][j] = fmaf(gd, u, -2.f * g * h * hd);                  \
        }                                                                     \
    }                                                                         \
    PACK_AFRAGS(C);                                                           \
} while (0)

// B0 fold + quad reduce + store
#define EW4(C) do {                                                           \
    float p00 = 0.f, p01 = 0.f, p02 = 0.f;                                    \
    float p10 = 0.f, p11 = 0.f, p12 = 0.f;                                    \
    _Pragma("unroll")                                                         \
    for (int nt = 0; nt < 8; nt++) {                                          \
        _Pragma("unroll")                                                     \
        for (int e = 0; e < 2; e++) {                                         \
            int k = nt * 8 + qc + e;                                          \
            float wa = w00f[k], wc = w01f[k];                                 \
            float2 hp = sp[C][(nt * 2 + e) * 32];                             \
            {                                                                 \
                float h = hp.x;                                               \
                float u = fmaf(-h, h, 1.f);                                   \
                float hd = u * wc;                                            \
                float g = zacc[C][nt][e], gd = dacc[C][nt][e];                \
                float d0 = g * u;                                             \
                float dd0 = fmaf(gd, u, -2.f * g * h * hd);                   \
                p00 = fmaf(d0, wa, p00);                                      \
                p01 = fmaf(dd0, wa, p01);                                     \
                p02 = fmaf(dd0, wc, p02);                                     \
            }                                                                 \
            {                                                                 \
                float h = hp.y;                                               \
                float u = fmaf(-h, h, 1.f);                                   \
                float hd = u * wc;                                            \
                float g = zacc[C][nt][e + 2], gd = dacc[C][nt][e + 2];        \
                float d0 = g * u;                                             \
                float dd0 = fmaf(gd, u, -2.f * g * h * hd);                   \
                p10 = fmaf(d0, wa, p10);                                      \
                p11 = fmaf(dd0, wa, p11);                                     \
                p12 = fmaf(dd0, wc, p12);                                     \
            }                                                                 \
        }                                                                     \
    }                                                                         \
    _Pragma("unroll")                                                         \
    for (int m = 1; m <= 2; m <<= 1) {                                        \
        p00 += __shfl_xor_sync(0xFFFFFFFFu, p00, m);                          \
        p01 += __shfl_xor_sync(0xFFFFFFFFu, p01, m);                          \
        p02 += __shfl_xor_sync(0xFFFFFFFFu, p02, m);                          \
        p10 += __shfl_xor_sync(0xFFFFFFFFu, p10, m);                          \
        p11 += __shfl_xor_sync(0xFFFFFFFFu, p11, m);                          \
        p12 += __shfl_xor_sync(0xFFFFFFFFu, p12, m);                          \
    }                                                                         \
    if ((lane & 3) == 0) {                                                    \
        if (ra[C] < B) {                                                      \
            float a = (p00 - p01 * xa[C].y) / (p02 + 0.1f);                   \
            out[ra[C]] = make_float2(xa[C].y, a);                             \
        }                                                                     \
        if (rb[C] < B) {                                                      \
            float a = (p10 - p11 * xb[C].y) / (p12 + 0.1f);                   \
            out[rb[C]] = make_float2(xb[C].y, a);                             \
        }                                                                     \
    }                                                                         \
} while (0)

__global__ void __launch_bounds__(TPB, 1)
lnn_mma(const float2* __restrict__ X,
        const float* __restrict__ W0, const float* __restrict__ b0,
        const float* __restrict__ W1, const float* __restrict__ b1,
        const float* __restrict__ W2, const float* __restrict__ b2,
        const float* __restrict__ W3,
        float2* __restrict__ out, int B, int npairs)
{
    extern __shared__ __align__(16) char sm[];
    uint2* bfr = (uint2*)sm;
    float* cs = (float*)(sm + CONST_OFF);
    float* w00f = cs;       float* w01f = cs + 64;
    float* b0f  = cs + 128; float* b1f  = cs + 192;
    float* b2f  = cs + 256; float* w3f  = cs + 320;
    float* stash = (float*)(sm + STASH_OFF);

    const int t = threadIdx.x;
    if (t < 64) {
        w00f[t] = W0[t];     w01f[t] = W0[64 + t];
        b0f[t]  = b0[t];     b1f[t]  = b1[t];
        b2f[t]  = b2[t];     w3f[t]  = W3[t];
    }
    // pre-pack weight B-fragments (single fp16):
    // s0: W1 (F1), s1: W2 (F2), s2: W2^T (B1), s3: W1^T (B0)
    for (int i = t; i < 4096; i += TPB) {
        int ln = i & 31, nt = (i >> 5) & 7, kt = (i >> 8) & 3, s = i >> 10;
        int k0 = kt * 16 + (ln & 3) * 2;
        int n  = nt * 8 + (ln >> 2);
        float v0, v1, v2, v3;
        if (s == 0) {
            v0 = W1[k0*64+n]; v1 = W1[(k0+1)*64+n];
            v2 = W1[(k0+8)*64+n]; v3 = W1[(k0+9)*64+n];
        } else if (s == 1) {
            v0 = W2[k0*64+n]; v1 = W2[(k0+1)*64+n];
            v2 = W2[(k0+8)*64+n]; v3 = W2[(k0+9)*64+n];
        } else if (s == 2) {
            v0 = W2[n*64+k0]; v1 = W2[n*64+k0+1];
            v2 = W2[n*64+k0+8]; v3 = W2[n*64+k0+9];
        } else {
            v0 = W1[n*64+k0]; v1 = W1[n*64+k0+1];
            v2 = W1[n*64+k0+8]; v3 = W1[n*64+k0+9];
        }
        bfr[i] = make_uint2(pack2h(v0, v1), pack2h(v2, v3));
    }
    __syncthreads();

    const int lane = t & 31, warp = t >> 5;
    const int qr = lane >> 2;
    const int qc = (lane & 3) * 2;
    // per-warp, per-chunk lane-interleaved float2 stash (48 float2/lane/chunk)
    float2* sp[2];
    sp[0] = (float2*)(stash + warp * (2 * 96 * 32)) + lane;
    sp[1] = sp[0] + 96 * 16;   // + 96*32 floats = 96*16 float2

    for (int pair = blockIdx.x * NW + warp; pair < npairs;
         pair += gridDim.x * NW) {
        int ra[2], rb[2];
        float2 xa[2], xb[2];
#pragma unroll
        for (int c = 0; c < 2; c++) {
            int chunk = pair * 2 + c;
            ra[c] = chunk * 16 + qr;
            rb[c] = ra[c] + 8;
            xa[c] = (ra[c] < B) ? X[ra[c]] : make_float2(0.f, 0.f);
            xb[c] = (rb[c] < B) ? X[rb[c]] : make_float2(0.f, 0.f);
        }

        u32 Ah[2][4][4], Th[2][4][4];
        float zacc[2][8][4], dacc[2][8][4];

        // software-pipelined: every EW block is independent of the MMA burst
        // that textually precedes it -> ptxas interleaves into idle issue slots
        EW0(0);  RUN_STAGE(0, 0);
        EW0(1);  RUN_STAGE(0, 1);
        EW1(0);  RUN_STAGE(1, 0);
        EW1(1);  RUN_STAGE(1, 1);
        EW2(0);  RUN_STAGE(2, 0);
        EW2(1);  RUN_STAGE(2, 1);
        EW3(0);  RUN_STAGE(3, 0);
        EW3(1);  RUN_STAGE(3, 1);
        EW4(0);
        EW4(1);
    }
}

extern "C" void kernel_launch(void* const* d_in, const int* in_sizes, int n_in,
                              void* d_out, int out_size) {
    const float* x  = (const float*)d_in[1];
    const float* W0 = (const float*)d_in[2];
    const float* b0 = (const float*)d_in[3];
    const float* W1 = (const float*)d_in[4];
    const float* b1 = (const float*)d_in[5];
    const float* W2 = (const float*)d_in[6];
    const float* b2 = (const float*)d_in[7];
    const float* W3 = (const float*)d_in[8];

    const int B = in_sizes[1] / 2;
    const int nchunks = (B + 15) / 16;
    const int npairs = (nchunks + 1) / 2;

    int dev = 0, sms = 148;
    cudaGetDevice(&dev);
    cudaDeviceGetAttribute(&sms, cudaDevAttrMultiProcessorCount, dev);
    int grid = (npairs + NW - 1) / NW;
    if (grid > sms) grid = sms;

    cudaFuncSetAttribute(lnn_mma, cudaFuncAttributeMaxDynamicSharedMemorySize,
                         SMEM_BYTES);
    lnn_mma<<<grid, TPB, SMEM_BYTES>>>((const float2*)x, W0, b0, W1, b1,
                                       W2, b2, W3, (float2*)d_out, B, npairs);
}

// round 14
// speedup vs baseline: 1.2397x; 1.2397x over previous
#include <cuda_runtime.h>
#include <cuda_fp16.h>

typedef unsigned int u32;

#define TPB 384
#define NW  12   // warps per CTA

// SMEM: B-frag bank 32KB | consts 1.5KB + ctab 0.5KB | stash 96KB
#define CONST_OFF 32768
#define CTAB_OFF  (CONST_OFF + 1536)
#define STASH_OFF (CONST_OFF + 2048)
#define SMEM_BYTES (STASH_OFF + NW * 2048 * 4)   // 133120

__device__ __forceinline__ float ftanh(float x) {
    float r; asm("tanh.approx.f32 %0, %1;" : "=f"(r) : "f"(x));
    return r;
}
__device__ __forceinline__ u32 pack2h(float a, float b) {
    __half2 h2 = __floats2half2_rn(a, b);
    return *reinterpret_cast<u32*>(&h2);
}
__device__ __forceinline__ __half2 u2h(u32 x) { return *reinterpret_cast<__half2*>(&x); }
__device__ __forceinline__ u32 h2u(__half2 x) { return *reinterpret_cast<u32*>(&x); }
__device__ __forceinline__ __half2 htanh2(__half2 a) {
    u32 r, x = h2u(a);
    asm("tanh.approx.f16x2 %0, %1;" : "=r"(r) : "r"(x));
    return u2h(r);
}
__device__ __forceinline__ __half2 hneg2b(__half2 a) {   // sign-flip via xor
    u32 x = h2u(a) ^ 0x80008000u;
    return u2h(x);
}

// accumulate form: D = A*B + D
__device__ __forceinline__ void mma16816(float* d, const u32* a, u32 b0, u32 b1) {
    asm volatile(
        "mma.sync.aligned.m16n8k16.row.col.f32.f16.f16.f32 "
        "{%0,%1,%2,%3},{%4,%5,%6,%7},{%8,%9},{%0,%1,%2,%3};"
        : "+f"(d[0]), "+f"(d[1]), "+f"(d[2]), "+f"(d[3])
        : "r"(a[0]), "r"(a[1]), "r"(a[2]), "r"(a[3]), "r"(b0), "r"(b1));
}
// zero-C form: D = A*B + 0
__device__ __forceinline__ void mma16816_z(float* d, const u32* a, u32 b0, u32 b1) {
    asm volatile(
        "mma.sync.aligned.m16n8k16.row.col.f32.f16.f16.f32 "
        "{%0,%1,%2,%3},{%4,%5,%6,%7},{%8,%9},{%10,%11,%12,%13};"
        : "=f"(d[0]), "=f"(d[1]), "=f"(d[2]), "=f"(d[3])
        : "r"(a[0]), "r"(a[1]), "r"(a[2]), "r"(a[3]), "r"(b0), "r"(b1),
          "f"(0.0f), "f"(0.0f), "f"(0.0f), "f"(0.0f));
}

// One GEMM stage: value = Ah x Bh, tangent = Th x Bh. kt=0 writes fresh.
#define RUN_STAGE(S) do {                                                     \
    _Pragma("unroll")                                                         \
    for (int kt = 0; kt < 4; kt++) {                                          \
        _Pragma("unroll")                                                     \
        for (int nt = 0; nt < 8; nt++) {                                      \
            uint2 bf = bfr[(((S) * 4 + kt) * 8 + nt) * 32 + lane];            \
            if (kt == 0) {                                                    \
                mma16816_z(zacc[nt], Ah[kt], bf.x, bf.y);                     \
                mma16816_z(dacc[nt], Th[kt], bf.x, bf.y);                     \
            } else {                                                          \
                mma16816(zacc[nt], Ah[kt], bf.x, bf.y);                       \
                mma16816(dacc[nt], Th[kt], bf.x, bf.y);                       \
            }                                                                 \
        }                                                                     \
    }                                                                         \
} while (0)

__global__ void __launch_bounds__(TPB, 1)
lnn_mma(const float2* __restrict__ X,
        const float* __restrict__ W0, const float* __restrict__ b0,
        const float* __restrict__ W1, const float* __restrict__ b1,
        const float* __restrict__ W2, const float* __restrict__ b2,
        const float* __restrict__ W3,
        float2* __restrict__ out, int B, int nchunks)
{
    extern __shared__ __align__(16) char sm[];
    uint2* bfr = (uint2*)sm;
    float* cs = (float*)(sm + CONST_OFF);
    float* w00f = cs;       float* w01f = cs + 64;
    float* b0f  = cs + 128; float* b1f  = cs + 192;
    float* b2f  = cs + 256; float* w3f  = cs + 320;
    uint4* ctab = (uint4*)(sm + CTAB_OFF);   // [32]: {b1h, b2h, w3h, m3h} per col-pair
    float* stash = (float*)(sm + STASH_OFF);

    const int t = threadIdx.x;
    if (t < 64) {
        w00f[t] = W0[t];     w01f[t] = W0[64 + t];
        b0f[t]  = b0[t];     b1f[t]  = b1[t];
        b2f[t]  = b2[t];     w3f[t]  = W3[t];
    }
    if (t < 32) {   // half2 const table per column pair (nt*4 + quadcol)
        int c0 = (t >> 2) * 8 + (t & 3) * 2;
        ctab[t] = make_uint4(pack2h(b1[c0], b1[c0 + 1]),
                             pack2h(b2[c0], b2[c0 + 1]),
                             pack2h(W3[c0], W3[c0 + 1]),
                             pack2h(-2.f * W3[c0], -2.f * W3[c0 + 1]));
    }
    // pre-pack weight B-fragments (single fp16):
    // s0: W1 (F1), s1: W2 (F2), s2: W2^T (B1), s3: W1^T (B0)
    for (int i = t; i < 4096; i += TPB) {
        int ln = i & 31, nt = (i >> 5) & 7, kt = (i >> 8) & 3, s = i >> 10;
        int k0 = kt * 16 + (ln & 3) * 2;
        int n  = nt * 8 + (ln >> 2);
        float v0, v1, v2, v3;
        if (s == 0) {
            v0 = W1[k0*64+n]; v1 = W1[(k0+1)*64+n];
            v2 = W1[(k0+8)*64+n]; v3 = W1[(k0+9)*64+n];
        } else if (s == 1) {
            v0 = W2[k0*64+n]; v1 = W2[(k0+1)*64+n];
            v2 = W2[(k0+8)*64+n]; v3 = W2[(k0+9)*64+n];
        } else if (s == 2) {
            v0 = W2[n*64+k0]; v1 = W2[n*64+k0+1];
            v2 = W2[n*64+k0+8]; v3 = W2[n*64+k0+9];
        } else {
            v0 = W1[n*64+k0]; v1 = W1[n*64+k0+1];
            v2 = W1[n*64+k0+8]; v3 = W1[n*64+k0+9];
        }
        bfr[i] = make_uint2(pack2h(v0, v1), pack2h(v2, v3));
    }
    __syncthreads();

    const int lane = t & 31, warp = t >> 5;
    const int qr = lane >> 2;          // row within 8-row group
    const int qc = (lane & 3) * 2;     // col pair base
    const int qp = lane & 3;           // quad col index
    // per-warp stash (2048 words): h0 float2[16]/lane then F1 uint2[16]/lane
    float*  wb  = stash + warp * 2048;
    float2* sp0 = (float2*)wb + lane;          // h0 pairs, idx*32
    uint2*  sp1 = (uint2*)(wb + 1024) + lane;  // (h2, -2*hd2) pairs, idx*32
    const __half2 one2 = __floats2half2_rn(1.f, 1.f);

    for (int chunk = blockIdx.x * NW + warp; chunk < nchunks;
         chunk += gridDim.x * NW) {
        const int r0 = chunk * 16 + qr, r1 = r0 + 8;
        float2 x0 = (r0 < B) ? X[r0] : make_float2(0.f, 0.f);
        float2 x1 = (r1 < B) ? X[r1] : make_float2(0.f, 0.f);
        const float q0 = x0.x, v0 = x0.y, q1 = x1.x, v1 = x1.y;

        u32 Ah[4][4], Th[4][4];

        // ===== F0 (fp32): h0/hd0 A-frags; stash h0 pairs =====
#pragma unroll
        for (int kt = 0; kt < 4; kt++) {
#pragma unroll
            for (int hh = 0; hh < 2; hh++) {
                int k = kt * 16 + hh * 8 + qc;
                int pb = (kt * 2 + hh) * 2;
                float wa = w00f[k], wb0 = w00f[k+1];
                float wc = w01f[k], wd = w01f[k+1];
                float ba = b0f[k],  bb = b0f[k+1];
                float z00 = fmaf(q0, wa, fmaf(v0, wc, ba));
                float z01 = fmaf(q0, wb0, fmaf(v0, wd, bb));
                float z10 = fmaf(q1, wa, fmaf(v1, wc, ba));
                float z11 = fmaf(q1, wb0, fmaf(v1, wd, bb));
                float h00 = ftanh(z00), h01 = ftanh(z01);
                float h10 = ftanh(z10), h11 = ftanh(z11);
                sp0[(pb + 0) * 32] = make_float2(h00, h10);
                sp0[(pb + 1) * 32] = make_float2(h01, h11);
                float d00 = fmaf(-h00, h00, 1.f) * wc;
                float d01 = fmaf(-h01, h01, 1.f) * wd;
                float d10 = fmaf(-h10, h10, 1.f) * wc;
                float d11 = fmaf(-h11, h11, 1.f) * wd;
                Ah[kt][hh*2]   = pack2h(h00, h01);
                Ah[kt][hh*2+1] = pack2h(h10, h11);
                Th[kt][hh*2]   = pack2h(d00, d01);
                Th[kt][hh*2+1] = pack2h(d10, d11);
            }
        }

        float zacc[8][4], dacc[8][4];
        RUN_STAGE(0);

        // ===== F1 (half2): z1 -> h1, hd1; stash (h2, -2*hd2); frags direct =====
#pragma unroll
        for (int nt = 0; nt < 8; nt++) {
            __half2 b1h = u2h(((const u32*)ctab)[(nt * 4 + qp) * 4 + 0]);
#pragma unroll
            for (int g = 0; g < 2; g++) {
                __half2 zh = __hadd2(u2h(pack2h(zacc[nt][2*g], zacc[nt][2*g+1])), b1h);
                __half2 h2v = htanh2(zh);
                __half2 uu = __hfma2(h2v, hneg2b(h2v), one2);
                __half2 dh = u2h(pack2h(dacc[nt][2*g], dacc[nt][2*g+1]));
                __half2 hd2 = __hmul2(uu, dh);
                __half2 s2 = hneg2b(__hadd2(hd2, hd2));   // -2*hd2
                sp1[(nt * 2 + g) * 32] = make_uint2(h2u(h2v), h2u(s2));
                Ah[nt >> 1][(nt & 1) * 2 + g] = h2u(h2v);
                Th[nt >> 1][(nt & 1) * 2 + g] = h2u(hd2);
            }
        }
        RUN_STAGE(1);

        // ===== F2 (half2): z2 -> d2, dd2; frags direct =====
#pragma unroll
        for (int nt = 0; nt < 8; nt++) {
            uint4 cc = ctab[nt * 4 + qp];
            __half2 b2h = u2h(cc.y), w3h = u2h(cc.z), m3h = u2h(cc.w);
#pragma unroll
            for (int g = 0; g < 2; g++) {
                __half2 zh = __hadd2(u2h(pack2h(zacc[nt][2*g], zacc[nt][2*g+1])), b2h);
                __half2 h2v = htanh2(zh);
                __half2 uu = __hfma2(h2v, hneg2b(h2v), one2);
                __half2 dh = u2h(pack2h(dacc[nt][2*g], dacc[nt][2*g+1]));
                __half2 hd2 = __hmul2(uu, dh);
                __half2 d2h = __hmul2(w3h, uu);                   // d2
                __half2 dd2h = __hmul2(__hmul2(m3h, h2v), hd2);   // -2*w3*h*hd
                Ah[nt >> 1][(nt & 1) * 2 + g] = h2u(d2h);
                Th[nt >> 1][(nt & 1) * 2 + g] = h2u(dd2h);
            }
        }
        RUN_STAGE(2);

        // ===== B1 (half2): g1,gd1 -> d1,dd1 via stashed (h2, -2hd2) =====
#pragma unroll
        for (int nt = 0; nt < 8; nt++) {
#pragma unroll
            for (int g = 0; g < 2; g++) {
                uint2 hp = sp1[(nt * 2 + g) * 32];
                __half2 h2v = u2h(hp.x), s2 = u2h(hp.y);
                __half2 uu = __hfma2(h2v, hneg2b(h2v), one2);
                __half2 g2 = u2h(pack2h(zacc[nt][2*g], zacc[nt][2*g+1]));
                __half2 gd2 = u2h(pack2h(dacc[nt][2*g], dacc[nt][2*g+1]));
                __half2 d1h = __hmul2(g2, uu);
                __half2 c2 = __hmul2(__hmul2(g2, h2v), s2);       // -2*g*h*hd
                __half2 dd1h = __hfma2(gd2, uu, c2);
                Ah[nt >> 1][(nt & 1) * 2 + g] = h2u(d1h);
                Th[nt >> 1][(nt & 1) * 2 + g] = h2u(dd1h);
            }
        }
        RUN_STAGE(3);

        // ===== B0 (fp32): g0,gd0 + stashed h0 -> per-row partials =====
        float p00 = 0.f, p01 = 0.f, p02 = 0.f;
        float p10 = 0.f, p11 = 0.f, p12 = 0.f;
#pragma unroll
        for (int nt = 0; nt < 8; nt++) {
#pragma unroll
            for (int e = 0; e < 2; e++) {
                int k = nt * 8 + qc + e;
                float wa = w00f[k], wc = w01f[k];
                float2 hp = sp0[(nt * 2 + e) * 32];
                {   // row0 (j = e)
                    float h = hp.x;
                    float u = fmaf(-h, h, 1.f);
                    float hd = u * wc;
                    float g = zacc[nt][e], gd = dacc[nt][e];
                    float d0 = g * u;
                    float dd0 = fmaf(gd, u, -2.f * g * h * hd);
                    p00 = fmaf(d0, wa, p00);
                    p01 = fmaf(dd0, wa, p01);
                    p02 = fmaf(dd0, wc, p02);
                }
                {   // row1 (j = e+2)
                    float h = hp.y;
                    float u = fmaf(-h, h, 1.f);
                    float hd = u * wc;
                    float g = zacc[nt][e + 2], gd = dacc[nt][e + 2];
                    float d0 = g * u;
                    float dd0 = fmaf(gd, u, -2.f * g * h * hd);
                    p10 = fmaf(d0, wa, p10);
                    p11 = fmaf(dd0, wa, p11);
                    p12 = fmaf(dd0, wc, p12);
                }
            }
        }
#pragma unroll
        for (int m = 1; m <= 2; m <<= 1) {
            p00 += __shfl_xor_sync(0xFFFFFFFFu, p00, m);
            p01 += __shfl_xor_sync(0xFFFFFFFFu, p01, m);
            p02 += __shfl_xor_sync(0xFFFFFFFFu, p02, m);
            p10 += __shfl_xor_sync(0xFFFFFFFFu, p10, m);
            p11 += __shfl_xor_sync(0xFFFFFFFFu, p11, m);
            p12 += __shfl_xor_sync(0xFFFFFFFFu, p12, m);
        }
        if ((lane & 3) == 0) {
            if (r0 < B) {
                float a = (p00 - p01 * v0) / (p02 + 0.1f);
                out[r0] = make_float2(v0, a);
            }
            if (r1 < B) {
                float a = (p10 - p11 * v1) / (p12 + 0.1f);
                out[r1] = make_float2(v1, a);
            }
        }
    }
}

extern "C" void kernel_launch(void* const* d_in, const int* in_sizes, int n_in,
                              void* d_out, int out_size) {
    const float* x  = (const float*)d_in[1];
    const float* W0 = (const float*)d_in[2];
    const float* b0 = (const float*)d_in[3];
    const float* W1 = (const float*)d_in[4];
    const float* b1 = (const float*)d_in[5];
    const float* W2 = (const float*)d_in[6];
    const float* b2 = (const float*)d_in[7];
    const float* W3 = (const float*)d_in[8];

    const int B = in_sizes[1] / 2;
    const int nchunks = (B + 15) / 16;

    int dev = 0, sms = 148;
    cudaGetDevice(&dev);
    cudaDeviceGetAttribute(&sms, cudaDevAttrMultiProcessorCount, dev);
    int grid = (nchunks + NW - 1) / NW;
    if (grid > sms) grid = sms;

    cudaFuncSetAttribute(lnn_mma, cudaFuncAttributeMaxDynamicSharedMemorySize,
                         SMEM_BYTES);
    lnn_mma<<<grid, TPB, SMEM_BYTES>>>((const float2*)x, W0, b0, W1, b1,
                                       W2, b2, W3, (float2*)d_out, B, nchunks);
}